// round 1
// baseline (speedup 1.0000x reference)
#include <cuda_runtime.h>
#include <cuda_bf16.h>
#include <math.h>

// Problem constants
#define BT    16384      // B*T tokens
#define DDIM  4096       // reduction dim
#define NCOL  320        // packed output cols: 256 gelu-gemm cols + 64 dd cols
#define OUTW  320        // output floats per token
#define EPSF  1.1920929e-07f

// ---- scratch (device globals; no runtime allocation) ----
__device__ float g_wpack[DDIM * NCOL];     // 5.24 MB
__device__ float g_h[(size_t)BT * NCOL];   // 21 MB

// ============================================================
// Kernel 1: pack weights  Wpack[d][col]
//   col   0..127 : dw1[d, g=0, c=0, k]        (k = col)
//   col 128..255 : dw1[d, g=0, c=2, k]        (k = col-128)
//   col 256..287 : dd[d, g=0, m']             (m' = col-256)
//   col 288..319 : dd[d, g=0, 64 + (col-288)]
// dw1 layout: (D, 1, 4, 128) -> d*512 + c*128 + k
// dd  layout: (D, 1, 128)    -> d*128 + m'
// ============================================================
__global__ void pack_kernel(const float* __restrict__ dw1,
                            const float* __restrict__ dd) {
    int idx = blockIdx.x * blockDim.x + threadIdx.x;
    if (idx >= DDIM * NCOL) return;
    int d = idx / NCOL;
    int col = idx % NCOL;
    float v;
    if (col < 128)       v = dw1[d * 512 + col];            // c=0
    else if (col < 256)  v = dw1[d * 512 + 256 + (col - 128)]; // c=2
    else if (col < 288)  v = dd[d * 128 + (col - 256)];
    else                 v = dd[d * 128 + 64 + (col - 288)];
    g_wpack[idx] = v;
}

// ============================================================
// Kernel 2: fp32 SGEMM  H = Q @ Wpack
//   Q: [BT, DDIM] row-major, Wpack: [DDIM, NCOL] row-major
// Tiles: BM=128, BN=64, BK=16; 256 threads; 8x4 per thread
// ============================================================
#define BM 128
#define BN 64
#define BK 16
#define TM 8
#define TN 4

__global__ __launch_bounds__(256) void gemm_kernel(const float* __restrict__ A) {
    __shared__ float As[BK][BM + 4];
    __shared__ float Bs[BK][BN];

    const int tid = threadIdx.x;
    const int bm = blockIdx.y * BM;
    const int bn = blockIdx.x * BN;

    const int tx = tid % 16;   // N direction (16 * TN = 64)
    const int ty = tid / 16;   // M direction (16 * TM = 128)

    // A tile load mapping: 128 rows x 16 cols = 2048 floats.
    // 4 threads per row (4 x float4), 64 rows/pass, 2 passes.
    const int a_row  = tid / 4;        // 0..63
    const int a_col4 = (tid % 4) * 4;  // 0,4,8,12
    // B tile load mapping: 16 rows x 64 cols = 1024 floats = 256 float4.
    const int b_row  = tid / 16;       // 0..15
    const int b_col4 = (tid % 16) * 4; // 0..60

    float acc[TM][TN];
#pragma unroll
    for (int i = 0; i < TM; i++)
#pragma unroll
        for (int j = 0; j < TN; j++) acc[i][j] = 0.0f;

    for (int k0 = 0; k0 < DDIM; k0 += BK) {
        // load A tile (transposed into As[k][m])
#pragma unroll
        for (int p = 0; p < 2; p++) {
            int r = a_row + p * 64;
            float4 v = *(const float4*)&A[(size_t)(bm + r) * DDIM + k0 + a_col4];
            As[a_col4 + 0][r] = v.x;
            As[a_col4 + 1][r] = v.y;
            As[a_col4 + 2][r] = v.z;
            As[a_col4 + 3][r] = v.w;
        }
        // load B tile
        {
            float4 v = *(const float4*)&g_wpack[(size_t)(k0 + b_row) * NCOL + bn + b_col4];
            *(float4*)&Bs[b_row][b_col4] = v;
        }
        __syncthreads();

#pragma unroll
        for (int k = 0; k < BK; k++) {
            float4 ra0 = *(const float4*)&As[k][ty * TM + 0];
            float4 ra1 = *(const float4*)&As[k][ty * TM + 4];
            float4 rb  = *(const float4*)&Bs[k][tx * TN];
            float ra[TM] = {ra0.x, ra0.y, ra0.z, ra0.w, ra1.x, ra1.y, ra1.z, ra1.w};
            float rbv[TN] = {rb.x, rb.y, rb.z, rb.w};
#pragma unroll
            for (int i = 0; i < TM; i++)
#pragma unroll
                for (int j = 0; j < TN; j++)
                    acc[i][j] = fmaf(ra[i], rbv[j], acc[i][j]);
        }
        __syncthreads();
    }

    // store H
#pragma unroll
    for (int i = 0; i < TM; i++) {
        float4 v = make_float4(acc[i][0], acc[i][1], acc[i][2], acc[i][3]);
        *(float4*)&g_h[(size_t)(bm + ty * TM + i) * NCOL + bn + tx * TN] = v;
    }
}

// ============================================================
// Kernel 3: epilogue. One warp per token.
//   h row layout: [0:128) c=0 pre-gelu, [128:256) c=2 pre-gelu,
//                 [256:288) dd pre, [288:320) dd post
//   out layout per token:
//     [0:64)    pre_qw1   (c=0, i=0..1, rmsnorm)
//     [64:128)  pre_qw2   (c=0, i=2..3, rmsnorm * norm_scale)
//     [128:160) pre_qdd   (tanh)
//     [160:224) post_qw1  (c=2, i=0..1)
//     [224:288) post_qw2  (c=2, i=2..3, * norm_scale)
//     [288:320) post_qdd  (tanh)
// qkw layout: (1,4,128,4,32) -> c*16384 + k*128 + i*32 + m
// ============================================================
__global__ __launch_bounds__(256) void epilogue_kernel(const float* __restrict__ qkw,
                                                       const float* __restrict__ norm_scale,
                                                       float* __restrict__ out) {
    const int lane = threadIdx.x & 31;
    const int w    = threadIdx.x >> 5;               // warp in block (0..7)
    const int tok  = blockIdx.x * 8 + w;
    if (tok >= BT) return;

    const float* h = g_h + (size_t)tok * NCOL;
    float* o = out + (size_t)tok * OUTW;
    const float scale = norm_scale[0];

    __shared__ float hg[8][256];
    // gelu (exact) on the 256 GEMM1 outputs
#pragma unroll
    for (int p = 0; p < 8; p++) {
        float x = h[lane + p * 32];
        hg[w][lane + p * 32] = 0.5f * x * (1.0f + erff(x * 0.70710678118654752f));
    }
    // dd path: tanh
    {
        float x1 = tanhf(h[256 + lane]);
        float x2 = tanhf(h[288 + lane]);
        o[128 + lane] = x1;   // pre_qdd
        o[288 + lane] = x2;   // post_qdd
    }
    __syncwarp();

    // two c-slices: cc=0 -> original c=0 (out base 0); cc=1 -> original c=2 (out base 160)
#pragma unroll
    for (int cc = 0; cc < 2; cc++) {
        const int corig = (cc == 0) ? 0 : 2;
        const float* qc = qkw + (size_t)corig * 16384;
        const float* hh = &hg[w][cc * 128];
        float acc0 = 0.f, acc1 = 0.f, acc2 = 0.f, acc3 = 0.f; // i = 0..3, m = lane
#pragma unroll 4
        for (int k = 0; k < 128; k++) {
            float hk = hh[k];
            const float* qr = qc + k * 128 + lane;
            acc0 = fmaf(hk, __ldg(qr + 0),  acc0);
            acc1 = fmaf(hk, __ldg(qr + 32), acc1);
            acc2 = fmaf(hk, __ldg(qr + 64), acc2);
            acc3 = fmaf(hk, __ldg(qr + 96), acc3);
        }
        const int base = (cc == 0) ? 0 : 160;
        float accs[4] = {acc0, acc1, acc2, acc3};
#pragma unroll
        for (int i = 0; i < 4; i++) {
            float ss = accs[i] * accs[i];
#pragma unroll
            for (int off = 16; off > 0; off >>= 1)
                ss += __shfl_xor_sync(0xFFFFFFFFu, ss, off);
            float r = rsqrtf(ss * (1.0f / 32.0f) + EPSF);
            float v = accs[i] * r;
            if (i < 2) {
                o[base + i * 32 + lane] = v;                  // w1
            } else {
                o[base + 64 + (i - 2) * 32 + lane] = v * scale; // w2
            }
        }
    }
}

// ============================================================
// launch
// ============================================================
extern "C" void kernel_launch(void* const* d_in, const int* in_sizes, int n_in,
                              void* d_out, int out_size) {
    const float* q    = (const float*)d_in[0];  // (4,4096,4096)
    const float* dw1  = (const float*)d_in[1];  // (4096,1,4,128)
    const float* qkw  = (const float*)d_in[2];  // (1,4,128,4,32)
    const float* dd   = (const float*)d_in[3];  // (4096,1,128)
    const float* nsc  = (const float*)d_in[4];  // (1,)
    float* out = (float*)d_out;

    pack_kernel<<<(DDIM * NCOL + 255) / 256, 256>>>(dw1, dd);

    dim3 grid(NCOL / BN, BT / BM);   // (5, 128)
    gemm_kernel<<<grid, 256>>>(q);

    epilogue_kernel<<<BT / 8, 256>>>(qkw, nsc, out);
}

// round 2
// speedup vs baseline: 1.0020x; 1.0020x over previous
#include <cuda_runtime.h>
#include <cuda_bf16.h>
#include <math.h>

// Problem constants
#define BT    16384      // B*T tokens
#define DDIM  4096       // reduction dim
#define NCOL  320        // packed output cols: 256 gelu-gemm cols + 64 dd cols
#define OUTW  320        // output floats per token
#define EPSF  1.1920929e-07f

// ---- scratch (device globals; no runtime allocation) ----
__device__ float g_wpack[DDIM * NCOL];     // 5.24 MB
__device__ float g_h[(size_t)BT * NCOL];   // 21 MB

// ============================================================
// Kernel 1: pack weights  Wpack[d][col]
//   col   0..127 : dw1[d, g=0, c=0, k]        (k = col)
//   col 128..255 : dw1[d, g=0, c=2, k]        (k = col-128)
//   col 256..287 : dd[d, g=0, m']             (m' = col-256)
//   col 288..319 : dd[d, g=0, 64 + (col-288)]
// dw1 layout: (D, 1, 4, 128) -> d*512 + c*128 + k
// dd  layout: (D, 1, 128)    -> d*128 + m'
// ============================================================
__global__ void pack_kernel(const float* __restrict__ dw1,
                            const float* __restrict__ dd) {
    int idx = blockIdx.x * blockDim.x + threadIdx.x;
    if (idx >= DDIM * NCOL) return;
    int d = idx / NCOL;
    int col = idx % NCOL;
    float v;
    if (col < 128)       v = dw1[d * 512 + col];            // c=0
    else if (col < 256)  v = dw1[d * 512 + 256 + (col - 128)]; // c=2
    else if (col < 288)  v = dd[d * 128 + (col - 256)];
    else                 v = dd[d * 128 + 64 + (col - 288)];
    g_wpack[idx] = v;
}

// ============================================================
// Kernel 2: fp32 SGEMM  H = Q @ Wpack
//   Q: [BT, DDIM] row-major, Wpack: [DDIM, NCOL] row-major
// Tiles: BM=128, BN=64, BK=16; 256 threads; 8x4 per thread
// ============================================================
#define BM 128
#define BN 64
#define BK 16
#define TM 8
#define TN 4

__global__ __launch_bounds__(256) void gemm_kernel(const float* __restrict__ A) {
    __shared__ float As[BK][BM + 4];
    __shared__ float Bs[BK][BN];

    const int tid = threadIdx.x;
    const int bm = blockIdx.y * BM;
    const int bn = blockIdx.x * BN;

    const int tx = tid % 16;   // N direction (16 * TN = 64)
    const int ty = tid / 16;   // M direction (16 * TM = 128)

    // A tile load mapping: 128 rows x 16 cols = 2048 floats.
    // 4 threads per row (4 x float4), 64 rows/pass, 2 passes.
    const int a_row  = tid / 4;        // 0..63
    const int a_col4 = (tid % 4) * 4;  // 0,4,8,12
    // B tile load mapping: 16 rows x 64 cols = 1024 floats = 256 float4.
    const int b_row  = tid / 16;       // 0..15
    const int b_col4 = (tid % 16) * 4; // 0..60

    float acc[TM][TN];
#pragma unroll
    for (int i = 0; i < TM; i++)
#pragma unroll
        for (int j = 0; j < TN; j++) acc[i][j] = 0.0f;

    for (int k0 = 0; k0 < DDIM; k0 += BK) {
        // load A tile (transposed into As[k][m])
#pragma unroll
        for (int p = 0; p < 2; p++) {
            int r = a_row + p * 64;
            float4 v = *(const float4*)&A[(size_t)(bm + r) * DDIM + k0 + a_col4];
            As[a_col4 + 0][r] = v.x;
            As[a_col4 + 1][r] = v.y;
            As[a_col4 + 2][r] = v.z;
            As[a_col4 + 3][r] = v.w;
        }
        // load B tile
        {
            float4 v = *(const float4*)&g_wpack[(size_t)(k0 + b_row) * NCOL + bn + b_col4];
            *(float4*)&Bs[b_row][b_col4] = v;
        }
        __syncthreads();

#pragma unroll
        for (int k = 0; k < BK; k++) {
            float4 ra0 = *(const float4*)&As[k][ty * TM + 0];
            float4 ra1 = *(const float4*)&As[k][ty * TM + 4];
            float4 rb  = *(const float4*)&Bs[k][tx * TN];
            float ra[TM] = {ra0.x, ra0.y, ra0.z, ra0.w, ra1.x, ra1.y, ra1.z, ra1.w};
            float rbv[TN] = {rb.x, rb.y, rb.z, rb.w};
#pragma unroll
            for (int i = 0; i < TM; i++)
#pragma unroll
                for (int j = 0; j < TN; j++)
                    acc[i][j] = fmaf(ra[i], rbv[j], acc[i][j]);
        }
        __syncthreads();
    }

    // store H
#pragma unroll
    for (int i = 0; i < TM; i++) {
        float4 v = make_float4(acc[i][0], acc[i][1], acc[i][2], acc[i][3]);
        *(float4*)&g_h[(size_t)(bm + ty * TM + i) * NCOL + bn + tx * TN] = v;
    }
}

// ============================================================
// Kernel 3: epilogue. One warp per token.
//   h row layout: [0:128) c=0 pre-gelu, [128:256) c=2 pre-gelu,
//                 [256:288) dd pre, [288:320) dd post
//   out layout per token:
//     [0:64)    pre_qw1   (c=0, i=0..1, rmsnorm)
//     [64:128)  pre_qw2   (c=0, i=2..3, rmsnorm * norm_scale)
//     [128:160) pre_qdd   (tanh)
//     [160:224) post_qw1  (c=2, i=0..1)
//     [224:288) post_qw2  (c=2, i=2..3, * norm_scale)
//     [288:320) post_qdd  (tanh)
// qkw layout: (1,4,128,4,32) -> c*16384 + k*128 + i*32 + m
// ============================================================
__global__ __launch_bounds__(256) void epilogue_kernel(const float* __restrict__ qkw,
                                                       const float* __restrict__ norm_scale,
                                                       float* __restrict__ out) {
    const int lane = threadIdx.x & 31;
    const int w    = threadIdx.x >> 5;               // warp in block (0..7)
    const int tok  = blockIdx.x * 8 + w;
    if (tok >= BT) return;

    const float* h = g_h + (size_t)tok * NCOL;
    float* o = out + (size_t)tok * OUTW;
    const float scale = norm_scale[0];

    __shared__ float hg[8][256];
    // gelu (exact) on the 256 GEMM1 outputs
#pragma unroll
    for (int p = 0; p < 8; p++) {
        float x = h[lane + p * 32];
        hg[w][lane + p * 32] = 0.5f * x * (1.0f + erff(x * 0.70710678118654752f));
    }
    // dd path: tanh
    {
        float x1 = tanhf(h[256 + lane]);
        float x2 = tanhf(h[288 + lane]);
        o[128 + lane] = x1;   // pre_qdd
        o[288 + lane] = x2;   // post_qdd
    }
    __syncwarp();

    // two c-slices: cc=0 -> original c=0 (out base 0); cc=1 -> original c=2 (out base 160)
#pragma unroll
    for (int cc = 0; cc < 2; cc++) {
        const int corig = (cc == 0) ? 0 : 2;
        const float* qc = qkw + (size_t)corig * 16384;
        const float* hh = &hg[w][cc * 128];
        float acc0 = 0.f, acc1 = 0.f, acc2 = 0.f, acc3 = 0.f; // i = 0..3, m = lane
#pragma unroll 4
        for (int k = 0; k < 128; k++) {
            float hk = hh[k];
            const float* qr = qc + k * 128 + lane;
            acc0 = fmaf(hk, __ldg(qr + 0),  acc0);
            acc1 = fmaf(hk, __ldg(qr + 32), acc1);
            acc2 = fmaf(hk, __ldg(qr + 64), acc2);
            acc3 = fmaf(hk, __ldg(qr + 96), acc3);
        }
        const int base = (cc == 0) ? 0 : 160;
        float accs[4] = {acc0, acc1, acc2, acc3};
#pragma unroll
        for (int i = 0; i < 4; i++) {
            float ss = accs[i] * accs[i];
#pragma unroll
            for (int off = 16; off > 0; off >>= 1)
                ss += __shfl_xor_sync(0xFFFFFFFFu, ss, off);
            float r = rsqrtf(ss * (1.0f / 32.0f) + EPSF);
            float v = accs[i] * r;
            if (i < 2) {
                o[base + i * 32 + lane] = v;                  // w1
            } else {
                o[base + 64 + (i - 2) * 32 + lane] = v * scale; // w2
            }
        }
    }
}

// ============================================================
// launch
// ============================================================
extern "C" void kernel_launch(void* const* d_in, const int* in_sizes, int n_in,
                              void* d_out, int out_size) {
    const float* q    = (const float*)d_in[0];  // (4,4096,4096)
    const float* dw1  = (const float*)d_in[1];  // (4096,1,4,128)
    const float* qkw  = (const float*)d_in[2];  // (1,4,128,4,32)
    const float* dd   = (const float*)d_in[3];  // (4096,1,128)
    const float* nsc  = (const float*)d_in[4];  // (1,)
    float* out = (float*)d_out;

    pack_kernel<<<(DDIM * NCOL + 255) / 256, 256>>>(dw1, dd);

    dim3 grid(NCOL / BN, BT / BM);   // (5, 128)
    gemm_kernel<<<grid, 256>>>(q);

    epilogue_kernel<<<BT / 8, 256>>>(qkw, nsc, out);
}

// round 5
// speedup vs baseline: 2.0458x; 2.0418x over previous
#include <cuda_runtime.h>
#include <cuda_bf16.h>
#include <math.h>
#include <stdint.h>

#define BT    16384
#define DDIM  4096
#define NCOLS 320
#define EPSF  1.1920929e-07f

#define BM  128
#define BN  64
#define BKE 32
#define KIT (DDIM / BKE)

#define SA_H 0
#define SA_L 8192
#define SB_H 16384
#define SB_L 20480
#define STG  24576

__device__ float g_h[(size_t)BT * NCOLS];
__device__ __nv_bfloat16 g_bh[(size_t)NCOLS * DDIM];
__device__ __nv_bfloat16 g_bl[(size_t)NCOLS * DDIM];

__device__ __forceinline__ uint32_t smem_u32(const void* p) {
    uint32_t a;
    asm("{ .reg .u64 t; cvta.to.shared.u64 t, %1; cvt.u32.u64 %0, t; }" : "=r"(a) : "l"(p));
    return a;
}

__device__ __forceinline__ uint32_t swz(int row, int u) {
    return (uint32_t)(row * 64 + ((u ^ ((row >> 1) & 3)) << 4));
}

__device__ __forceinline__ void cvt_hl(float a, float b, uint32_t& h, uint32_t& l) {
    asm("cvt.rn.bf16x2.f32 %0, %1, %2;" : "=r"(h) : "f"(b), "f"(a));
    float ha = __uint_as_float(h << 16);
    float hb = __uint_as_float(h & 0xFFFF0000u);
    asm("cvt.rn.bf16x2.f32 %0, %1, %2;" : "=r"(l) : "f"(b - hb), "f"(a - ha));
}

__device__ __forceinline__ void st4(uint32_t a, uint32_t x, uint32_t y, uint32_t z, uint32_t w) {
    asm volatile("st.shared.v4.b32 [%0], {%1,%2,%3,%4};" :: "r"(a), "r"(x), "r"(y), "r"(z), "r"(w));
}

__device__ __forceinline__ void cpa16(uint32_t dst, const void* src) {
    asm volatile("cp.async.cg.shared.global [%0], [%1], 16;"
        :: "r"(dst), "l"((size_t)__cvta_generic_to_global(src)) : "memory");
}

#define CP_COMMIT() asm volatile("cp.async.commit_group;" ::: "memory")
#define CP_WAIT1()  asm volatile("cp.async.wait_group 1;" ::: "memory")

#define LDM4(r, a) \
    asm volatile("ldmatrix.sync.aligned.m8n8.x4.shared.b16 {%0,%1,%2,%3}, [%4];" \
        : "=r"((r)[0]), "=r"((r)[1]), "=r"((r)[2]), "=r"((r)[3]) : "r"(a))

#define MMA(c, a, b) \
    asm volatile("mma.sync.aligned.m16n8k16.row.col.f32.bf16.bf16.f32 " \
        "{%0,%1,%2,%3},{%4,%5,%6,%7},{%8,%9},{%0,%1,%2,%3};" \
        : "+f"((c)[0]), "+f"((c)[1]), "+f"((c)[2]), "+f"((c)[3]) \
        : "r"((a)[0]), "r"((a)[1]), "r"((a)[2]), "r"((a)[3]), "r"((b)[0]), "r"((b)[1]))

// ---- kernel 1: pack selected W columns, split into bf16 hi/lo ----
// row n of B^T [320][4096]:
//   n<128: dw1[k][0][n] ; n<256: dw1[k][2][n-128] ; n<288: dd[k][n-256] ; else dd[k][64+n-288]
__global__ void pack_b_kernel(const float* __restrict__ dw1, const float* __restrict__ dd) {
    int idx = blockIdx.x * blockDim.x + threadIdx.x;
    if (idx >= NCOLS * DDIM) return;
    int n = idx / DDIM, k = idx % DDIM;
    float v;
    if (n < 128)      v = dw1[k * 512 + n];
    else if (n < 256) v = dw1[k * 512 + 256 + (n - 128)];
    else if (n < 288) v = dd[k * 128 + (n - 256)];
    else              v = dd[k * 128 + 64 + (n - 288)];
    __nv_bfloat16 h = __float2bfloat16(v);
    g_bh[idx] = h;
    g_bl[idx] = __float2bfloat16(v - __bfloat162float(h));
}

// ---- kernel 2: split-bf16 HMMA GEMM  H[16384,320] = Q * Wpack ----
__global__ void __launch_bounds__(256, 2) gemm_hmma(const float* __restrict__ Q) {
    __shared__ __align__(1024) unsigned char sm[2 * STG];
    const uint32_t sb = smem_u32(sm);
    const int tid = threadIdx.x, lane = tid & 31, wid = tid >> 5;
    const int wm = wid & 3, wn = wid >> 2;
    const int m0 = blockIdx.y * BM, bn = blockIdx.x * BN;

    // A load/convert mapping: thread -> (row = tid>>1, 16 consecutive k at (tid&1)*16)
    const int arow = tid >> 1, au0 = (tid & 1) * 2;
    const float* aptr = Q + (size_t)(m0 + arow) * DDIM + au0 * 8;
    const uint32_t sts_a0 = swz(arow, au0), sts_a1 = swz(arow, au0 + 1);

    // B cp.async mapping: thread -> 16B of hi and 16B of lo
    const int brow = tid >> 2, bu = tid & 3;
    const __nv_bfloat16* bsrc_h = g_bh + (size_t)(bn + brow) * DDIM + bu * 8;
    const __nv_bfloat16* bsrc_l = g_bl + (size_t)(bn + brow) * DDIM + bu * 8;
    const uint32_t bdst_h = SB_H + swz(brow, bu);
    const uint32_t bdst_l = SB_L + swz(brow, bu);

    // ldmatrix address precompute
    const int la = lane >> 4;           // A: k8-unit select
    const int lb = (lane >> 3) & 1;     // B: k8-unit select
    const int rA0 = wm * 32 + (lane & 15);
    const int rB0 = wn * 32 + ((lane >> 4) & 1) * 8 + (lane & 7);
    uint32_t a_r64[2], b_r64[2];
    int a_rsw[2], b_rsw[2];
#pragma unroll
    for (int t = 0; t < 2; t++) {
        int ra = rA0 + t * 16, rb = rB0 + t * 16;
        a_r64[t] = ra * 64; a_rsw[t] = (ra >> 1) & 3;
        b_r64[t] = rb * 64; b_rsw[t] = (rb >> 1) & 3;
    }

    float4 ra0, ra1, ra2, ra3;
    float acc[2][4][4];
#pragma unroll
    for (int i = 0; i < 2; i++)
#pragma unroll
        for (int j = 0; j < 4; j++)
#pragma unroll
            for (int v = 0; v < 4; v++) acc[i][j][v] = 0.0f;

#define LDGA(i) do { const float4* _p = (const float4*)(aptr + (size_t)(i) * BKE); \
    ra0 = __ldg(_p); ra1 = __ldg(_p + 1); ra2 = __ldg(_p + 2); ra3 = __ldg(_p + 3); } while (0)

#define CPB(i, stg) do { \
    cpa16((stg) + bdst_h, bsrc_h + (size_t)(i) * BKE); \
    cpa16((stg) + bdst_l, bsrc_l + (size_t)(i) * BKE); } while (0)

#define STSA(stg) do { \
    uint32_t h0, h1, h2, h3, l0, l1, l2, l3; \
    cvt_hl(ra0.x, ra0.y, h0, l0); cvt_hl(ra0.z, ra0.w, h1, l1); \
    cvt_hl(ra1.x, ra1.y, h2, l2); cvt_hl(ra1.z, ra1.w, h3, l3); \
    st4((stg) + SA_H + sts_a0, h0, h1, h2, h3); \
    st4((stg) + SA_L + sts_a0, l0, l1, l2, l3); \
    cvt_hl(ra2.x, ra2.y, h0, l0); cvt_hl(ra2.z, ra2.w, h1, l1); \
    cvt_hl(ra3.x, ra3.y, h2, l2); cvt_hl(ra3.z, ra3.w, h3, l3); \
    st4((stg) + SA_H + sts_a1, h0, h1, h2, h3); \
    st4((stg) + SA_L + sts_a1, l0, l1, l2, l3); } while (0)

    // prologue: stage0 <- iter0, stage1 <- iter1
    LDGA(0);
    CPB(0, sb);
    CP_COMMIT();
    STSA(sb);
    LDGA(1);
    CPB(1, sb + STG);
    CP_COMMIT();
    CP_WAIT1();
    __syncthreads();

    for (int i = 0; i < KIT; i++) {
        const uint32_t sbase = sb + (i & 1) * STG;
        // ---- MMA on stage (i&1) ----
#pragma unroll
        for (int kk = 0; kk < 2; kk++) {
            uint32_t ah[2][4], al[2][4], bh[2][4], bl[2][4];
#pragma unroll
            for (int t = 0; t < 2; t++) {
                uint32_t au = (((kk << 1) + la) ^ a_rsw[t]) << 4;
                uint32_t bu = (((kk << 1) + lb) ^ b_rsw[t]) << 4;
                LDM4(ah[t], sbase + SA_H + a_r64[t] + au);
                LDM4(al[t], sbase + SA_L + a_r64[t] + au);
                LDM4(bh[t], sbase + SB_H + b_r64[t] + bu);
                LDM4(bl[t], sbase + SB_L + b_r64[t] + bu);
            }
#pragma unroll
            for (int mt = 0; mt < 2; mt++)
#pragma unroll
                for (int nt = 0; nt < 4; nt++) {
                    const uint32_t* bfh = &bh[nt >> 1][(nt & 1) * 2];
                    const uint32_t* bfl = &bl[nt >> 1][(nt & 1) * 2];
                    MMA(acc[mt][nt], ah[mt], bfh);
                    MMA(acc[mt][nt], ah[mt], bfl);
                    MMA(acc[mt][nt], al[mt], bfh);
                }
        }
        __syncthreads();
        if (i + 1 < KIT) STSA(sb + ((i + 1) & 1) * STG);
        if (i + 2 < KIT) { LDGA(i + 2); CPB(i + 2, sbase); }
        CP_COMMIT();
        CP_WAIT1();
        __syncthreads();
    }

    // ---- store H ----
#pragma unroll
    for (int mt = 0; mt < 2; mt++) {
        int row = m0 + wm * 32 + mt * 16 + (lane >> 2);
#pragma unroll
        for (int nt = 0; nt < 4; nt++) {
            int col = bn + wn * 32 + nt * 8 + (lane & 3) * 2;
            *(float2*)&g_h[(size_t)row * NCOLS + col] =
                make_float2(acc[mt][nt][0], acc[mt][nt][1]);
            *(float2*)&g_h[(size_t)(row + 8) * NCOLS + col] =
                make_float2(acc[mt][nt][2], acc[mt][nt][3]);
        }
    }
}

// ---- kernel 3: per-token epilogue ----
__global__ __launch_bounds__(256) void epilogue_kernel(const float* __restrict__ qkw,
                                                       const float* __restrict__ norm_scale,
                                                       float* __restrict__ out) {
    const int lane = threadIdx.x & 31, w = threadIdx.x >> 5;
    const int tok = blockIdx.x * 8 + w;
    if (tok >= BT) return;
    const float* h = g_h + (size_t)tok * NCOLS;
    float* o = out + (size_t)tok * NCOLS;
    const float scale = norm_scale[0];
    const int ii = lane >> 3, m4 = (lane & 7) * 4;

    __shared__ float hg[8][256];
#pragma unroll
    for (int p = 0; p < 8; p++) {
        float x = h[lane + p * 32];
        hg[w][lane + p * 32] = 0.5f * x * (1.0f + erff(x * 0.70710678118654752f));
    }
    o[128 + lane] = tanhf(h[256 + lane]);
    o[288 + lane] = tanhf(h[288 + lane]);
    __syncwarp();

#pragma unroll
    for (int cc = 0; cc < 2; cc++) {
        const float* qc = qkw + (size_t)(cc * 2) * 16384 + ii * 32 + m4;
        const float* hh = &hg[w][cc * 128];
        float a0 = 0.f, a1 = 0.f, a2 = 0.f, a3 = 0.f;
#pragma unroll 4
        for (int k = 0; k < 128; k++) {
            float hk = hh[k];
            float4 wv = __ldg((const float4*)(qc + k * 128));
            a0 = fmaf(hk, wv.x, a0); a1 = fmaf(hk, wv.y, a1);
            a2 = fmaf(hk, wv.z, a2); a3 = fmaf(hk, wv.w, a3);
        }
        float ss = a0 * a0 + a1 * a1 + a2 * a2 + a3 * a3;
#pragma unroll
        for (int m = 1; m < 8; m <<= 1) ss += __shfl_xor_sync(0xFFFFFFFFu, ss, m);
        float r = rsqrtf(ss * (1.0f / 32.0f) + EPSF);
        if (ii >= 2) r *= scale;
        int base = cc * 160 + ii * 32 + m4;
        o[base] = a0 * r; o[base + 1] = a1 * r; o[base + 2] = a2 * r; o[base + 3] = a3 * r;
    }
}

extern "C" void kernel_launch(void* const* d_in, const int* in_sizes, int n_in,
                              void* d_out, int out_size) {
    const float* q   = (const float*)d_in[0];
    const float* dw1 = (const float*)d_in[1];
    const float* qkw = (const float*)d_in[2];
    const float* dd  = (const float*)d_in[3];
    const float* nsc = (const float*)d_in[4];
    float* out = (float*)d_out;

    pack_b_kernel<<<(NCOLS * DDIM + 255) / 256, 256>>>(dw1, dd);
    dim3 grid(NCOLS / BN, BT / BM);   // (5, 128)
    gemm_hmma<<<grid, 256>>>(q);
    epilogue_kernel<<<BT / 8, 256>>>(qkw, nsc, out);
}

// round 6
// speedup vs baseline: 2.6489x; 1.2948x over previous
#include <cuda_runtime.h>
#include <cuda_bf16.h>
#include <math.h>
#include <stdint.h>

#define BT    16384
#define DDIM  4096
#define NCOLS 320
#define EPSF  1.1920929e-07f

#define BM  128
#define BK  32
#define KIT (DDIM / BK)

// smem layout per stage: A 256 rows x 64B (hi rows 0-127, lo 128-255) = 16KB
//                        B 640 rows x 64B (hi rows 0-319, lo 320-639) = 40KB
#define SA   0
#define SB   16384
#define STG  57344
#define SMEM_TOTAL (2 * STG)

__device__ float g_h[(size_t)BT * NCOLS];
__device__ __nv_bfloat16 g_bh[(size_t)NCOLS * DDIM];
__device__ __nv_bfloat16 g_bl[(size_t)NCOLS * DDIM];

__device__ __forceinline__ uint32_t smem_u32(const void* p) {
    uint32_t a;
    asm("{ .reg .u64 t; cvta.to.shared.u64 t, %1; cvt.u32.u64 %0, t; }" : "=r"(a) : "l"(p));
    return a;
}
__device__ __forceinline__ uint32_t swz(int row, int u) {
    return (uint32_t)(row * 64 + ((u ^ ((row >> 1) & 3)) << 4));
}
__device__ __forceinline__ void cvt_hl(float a, float b, uint32_t& h, uint32_t& l) {
    asm("cvt.rn.bf16x2.f32 %0, %1, %2;" : "=r"(h) : "f"(b), "f"(a));
    float ha = __uint_as_float(h << 16);
    float hb = __uint_as_float(h & 0xFFFF0000u);
    asm("cvt.rn.bf16x2.f32 %0, %1, %2;" : "=r"(l) : "f"(b - hb), "f"(a - ha));
}
__device__ __forceinline__ void st4(uint32_t a, uint32_t x, uint32_t y, uint32_t z, uint32_t w) {
    asm volatile("st.shared.v4.b32 [%0], {%1,%2,%3,%4};" :: "r"(a), "r"(x), "r"(y), "r"(z), "r"(w));
}
__device__ __forceinline__ void cpa16(uint32_t dst, const void* src) {
    asm volatile("cp.async.cg.shared.global [%0], [%1], 16;"
        :: "r"(dst), "l"((size_t)__cvta_generic_to_global(src)) : "memory");
}
#define CP_COMMIT() asm volatile("cp.async.commit_group;" ::: "memory")
#define CP_WAIT1()  asm volatile("cp.async.wait_group 1;" ::: "memory")

#define LDM4(r, a) \
    asm volatile("ldmatrix.sync.aligned.m8n8.x4.shared.b16 {%0,%1,%2,%3}, [%4];" \
        : "=r"((r)[0]), "=r"((r)[1]), "=r"((r)[2]), "=r"((r)[3]) : "r"(a))

#define MMA(c, a, b) \
    asm volatile("mma.sync.aligned.m16n8k16.row.col.f32.bf16.bf16.f32 " \
        "{%0,%1,%2,%3},{%4,%5,%6,%7},{%8,%9},{%0,%1,%2,%3};" \
        : "+f"((c)[0]), "+f"((c)[1]), "+f"((c)[2]), "+f"((c)[3]) \
        : "r"((a)[0]), "r"((a)[1]), "r"((a)[2]), "r"((a)[3]), "r"((b)[0]), "r"((b)[1]))

// ---- kernel 1: pack selected W columns, split into bf16 hi/lo ----
__global__ void pack_b_kernel(const float* __restrict__ dw1, const float* __restrict__ dd) {
    int idx = blockIdx.x * blockDim.x + threadIdx.x;
    if (idx >= NCOLS * DDIM) return;
    int n = idx / DDIM, k = idx % DDIM;
    float v;
    if (n < 128)      v = dw1[k * 512 + n];
    else if (n < 256) v = dw1[k * 512 + 256 + (n - 128)];
    else if (n < 288) v = dd[k * 128 + (n - 256)];
    else              v = dd[k * 128 + 64 + (n - 288)];
    __nv_bfloat16 h = __float2bfloat16(v);
    g_bh[idx] = h;
    g_bl[idx] = __float2bfloat16(v - __bfloat162float(h));
}

// ---- kernel 2: split-bf16 HMMA GEMM, full-N per CTA ----
__global__ void __launch_bounds__(512, 1) gemm_hmma(const float* __restrict__ Q) {
    extern __shared__ __align__(1024) unsigned char sm[];
    const uint32_t sb = smem_u32(sm);
    const int tid = threadIdx.x, lane = tid & 31, wid = tid >> 5;
    const int wm = wid & 3, wn = wid >> 2;
    const int m0 = blockIdx.x * BM;

    // A convert mapping: thread -> (row = tid>>2, 8 consecutive k at (tid&3)*8)
    const int arow = tid >> 2, au = tid & 3;
    const float* aptr = Q + (size_t)(m0 + arow) * DDIM + au * 8;
    const uint32_t a_dst_h = SA + swz(arow, au);
    const uint32_t a_dst_l = SA + swz(arow + 128, au);

    // B cp.async mapping: 5 x 16B per thread per iter
    const __nv_bfloat16* bsrc[5];
    uint32_t bdst[5];
#pragma unroll
    for (int j = 0; j < 5; j++) {
        int idx = tid + j * 512;
        int row = idx >> 2, u = idx & 3;
        bsrc[j] = (row < NCOLS ? g_bh + (size_t)row * DDIM
                               : g_bl + (size_t)(row - NCOLS) * DDIM) + u * 8;
        bdst[j] = SB + swz(row, u);
    }

    // ldmatrix address precompute
    const int la = lane >> 4;        // A k8-unit select
    const int lb = (lane >> 3) & 1;  // B k8-unit select
    uint32_t a_r64[2]; int a_rsw[2];
#pragma unroll
    for (int t = 0; t < 2; t++) {
        int ra = wm * 32 + (lane & 15) + t * 16;
        a_r64[t] = ra * 64; a_rsw[t] = (ra >> 1) & 3;
    }
    uint32_t b_r64[5]; int b_rsw[5];
#pragma unroll
    for (int t = 0; t < 5; t++) {
        int rb = wn * 80 + t * 16 + ((lane >> 4) & 1) * 8 + (lane & 7);
        b_r64[t] = rb * 64; b_rsw[t] = (rb >> 1) & 3;
    }

    float4 ra0, ra1;
    float acc[2][10][4];
#pragma unroll
    for (int i = 0; i < 2; i++)
#pragma unroll
        for (int j = 0; j < 10; j++)
#pragma unroll
            for (int v = 0; v < 4; v++) acc[i][j][v] = 0.0f;

#define LDGA(i) do { const float4* _p = (const float4*)(aptr + (size_t)(i) * BK); \
    ra0 = __ldg(_p); ra1 = __ldg(_p + 1); } while (0)

#define STSA(stg) do { \
    uint32_t h0, h1, h2, h3, l0, l1, l2, l3; \
    cvt_hl(ra0.x, ra0.y, h0, l0); cvt_hl(ra0.z, ra0.w, h1, l1); \
    cvt_hl(ra1.x, ra1.y, h2, l2); cvt_hl(ra1.z, ra1.w, h3, l3); \
    st4((stg) + a_dst_h, h0, h1, h2, h3); \
    st4((stg) + a_dst_l, l0, l1, l2, l3); } while (0)

#define CPB(i, stg) do { \
    _Pragma("unroll") \
    for (int _j = 0; _j < 5; _j++) cpa16((stg) + bdst[_j], bsrc[_j] + (size_t)(i) * BK); } while (0)

    // prologue
    LDGA(0); CPB(0, sb); CP_COMMIT();
    STSA(sb);
    LDGA(1); CPB(1, sb + STG); CP_COMMIT();
    CP_WAIT1();
    __syncthreads();

    for (int i = 0; i < KIT; i++) {
        const uint32_t sbase = sb + (i & 1) * STG;
#pragma unroll
        for (int kk = 0; kk < 2; kk++) {
            uint32_t ah[2][4], al[2][4];
#pragma unroll
            for (int t = 0; t < 2; t++) {
                uint32_t auo = (uint32_t)((((kk << 1) + la) ^ a_rsw[t]) << 4);
                LDM4(ah[t], sbase + SA + a_r64[t] + auo);
                LDM4(al[t], sbase + SA + a_r64[t] + 8192 + auo);
            }
#pragma unroll
            for (int t5 = 0; t5 < 5; t5++) {
                uint32_t buo = (uint32_t)((((kk << 1) + lb) ^ b_rsw[t5]) << 4);
                uint32_t bh4[4], bl4[4];
                LDM4(bh4, sbase + SB + b_r64[t5] + buo);
                LDM4(bl4, sbase + SB + b_r64[t5] + 20480 + buo);
#pragma unroll
                for (int mt = 0; mt < 2; mt++)
#pragma unroll
                    for (int s = 0; s < 2; s++) {
                        MMA(acc[mt][t5 * 2 + s], ah[mt], &bh4[s * 2]);
                        MMA(acc[mt][t5 * 2 + s], ah[mt], &bl4[s * 2]);
                        MMA(acc[mt][t5 * 2 + s], al[mt], &bh4[s * 2]);
                    }
            }
        }
        __syncthreads();
        if (i + 1 < KIT) STSA(sb + ((i + 1) & 1) * STG);
        if (i + 2 < KIT) { LDGA(i + 2); CPB(i + 2, sbase); }
        CP_COMMIT();
        CP_WAIT1();
        __syncthreads();
    }

    // store H
#pragma unroll
    for (int mt = 0; mt < 2; mt++) {
        int row = m0 + wm * 32 + mt * 16 + (lane >> 2);
#pragma unroll
        for (int nt = 0; nt < 10; nt++) {
            int col = wn * 80 + nt * 8 + (lane & 3) * 2;
            *(float2*)&g_h[(size_t)row * NCOLS + col] =
                make_float2(acc[mt][nt][0], acc[mt][nt][1]);
            *(float2*)&g_h[(size_t)(row + 8) * NCOLS + col] =
                make_float2(acc[mt][nt][2], acc[mt][nt][3]);
        }
    }
}

// ---- kernel 3: per-token epilogue ----
__global__ __launch_bounds__(256) void epilogue_kernel(const float* __restrict__ qkw,
                                                       const float* __restrict__ norm_scale,
                                                       float* __restrict__ out) {
    const int lane = threadIdx.x & 31, w = threadIdx.x >> 5;
    const int tok = blockIdx.x * 8 + w;
    if (tok >= BT) return;
    const float* h = g_h + (size_t)tok * NCOLS;
    float* o = out + (size_t)tok * NCOLS;
    const float scale = norm_scale[0];
    const int ii = lane >> 3, m4 = (lane & 7) * 4;

    __shared__ float hg[8][256];
#pragma unroll
    for (int p = 0; p < 8; p++) {
        float x = h[lane + p * 32];
        hg[w][lane + p * 32] = 0.5f * x * (1.0f + erff(x * 0.70710678118654752f));
    }
    o[128 + lane] = tanhf(h[256 + lane]);
    o[288 + lane] = tanhf(h[288 + lane]);
    __syncwarp();

#pragma unroll
    for (int cc = 0; cc < 2; cc++) {
        const float* qc = qkw + (size_t)(cc * 2) * 16384 + ii * 32 + m4;
        const float* hh = &hg[w][cc * 128];
        float a0 = 0.f, a1 = 0.f, a2 = 0.f, a3 = 0.f;
#pragma unroll 4
        for (int k = 0; k < 128; k++) {
            float hk = hh[k];
            float4 wv = __ldg((const float4*)(qc + k * 128));
            a0 = fmaf(hk, wv.x, a0); a1 = fmaf(hk, wv.y, a1);
            a2 = fmaf(hk, wv.z, a2); a3 = fmaf(hk, wv.w, a3);
        }
        float ss = a0 * a0 + a1 * a1 + a2 * a2 + a3 * a3;
#pragma unroll
        for (int m = 1; m < 8; m <<= 1) ss += __shfl_xor_sync(0xFFFFFFFFu, ss, m);
        float r = rsqrtf(ss * (1.0f / 32.0f) + EPSF);
        if (ii >= 2) r *= scale;
        int base = cc * 160 + ii * 32 + m4;
        o[base] = a0 * r; o[base + 1] = a1 * r; o[base + 2] = a2 * r; o[base + 3] = a3 * r;
    }
}

extern "C" void kernel_launch(void* const* d_in, const int* in_sizes, int n_in,
                              void* d_out, int out_size) {
    const float* q   = (const float*)d_in[0];
    const float* dw1 = (const float*)d_in[1];
    const float* qkw = (const float*)d_in[2];
    const float* dd  = (const float*)d_in[3];
    const float* nsc = (const float*)d_in[4];
    float* out = (float*)d_out;

    cudaFuncSetAttribute(gemm_hmma, cudaFuncAttributeMaxDynamicSharedMemorySize, SMEM_TOTAL);
    pack_b_kernel<<<(NCOLS * DDIM + 255) / 256, 256>>>(dw1, dd);
    gemm_hmma<<<BT / BM, 512, SMEM_TOTAL>>>(q);
    epilogue_kernel<<<BT / 8, 256>>>(qkw, nsc, out);
}